// round 2
// baseline (speedup 1.0000x reference)
#include <cuda_runtime.h>

// Problem constants
#define B_  4
#define S_  2048
#define D_  1024
#define H_  16
#define DK_ 64

static const long long BS_LL   = (long long)B_ * S_;          // 8192
static const long long BSD_LL  = (long long)B_ * S_ * D_;     // 8388608
static const long long ATTN_LL = (long long)B_ * H_ * S_ * S_; // 268435456

// Scratch (allocation-free rule: __device__ globals)
__device__ float g_q[(size_t)BSD_LL];   // Q projected; reused as Ctx later
__device__ float g_k[(size_t)BSD_LL];
__device__ float g_v[(size_t)BSD_LL];
__device__ float g_attn_fallback[(size_t)ATTN_LL]; // used only if out_size doesn't cover attn

#define BM 64
#define BN 64
#define BK 16

// C[m,n] = scale * sum_k A[m,k]*B[n,k]  (+ bias[n])
// A rows: K contiguous (lda), B rows: K contiguous (ldb). Batched via z with
// (b,h) decomposition: ptr += (z/H)*s?b + (z%H)*s?h.
__global__ __launch_bounds__(256) void gemm_nt(
    const float* __restrict__ A, const float* __restrict__ Bm,
    const float* __restrict__ bias, float* __restrict__ C,
    int M, int N, int K, int lda, int ldb, int ldc,
    long long sAb, long long sAh, long long sBb, long long sBh,
    long long sCb, long long sCh, int Hdim, float scale)
{
    __shared__ float As[BK][BM + 4];
    __shared__ float Bs[BK][BN + 4];

    const int bz = blockIdx.z;
    const int bi = bz / Hdim, hi = bz % Hdim;
    A  += (long long)bi * sAb + (long long)hi * sAh;
    Bm += (long long)bi * sBb + (long long)hi * sBh;
    C  += (long long)bi * sCb + (long long)hi * sCh;

    const int tid = threadIdx.x;
    const int tx = tid & 15, ty = tid >> 4;
    const int row0 = blockIdx.y * BM;
    const int col0 = blockIdx.x * BN;

    float acc[4][4];
#pragma unroll
    for (int i = 0; i < 4; i++)
#pragma unroll
        for (int j = 0; j < 4; j++) acc[i][j] = 0.0f;

    const int lm = tid >> 2;          // 0..63
    const int lk = (tid & 3) * 4;     // 0,4,8,12

    for (int kt = 0; kt < K; kt += BK) {
        float4 av = *reinterpret_cast<const float4*>(A  + (long long)(row0 + lm) * lda + kt + lk);
        float4 bv = *reinterpret_cast<const float4*>(Bm + (long long)(col0 + lm) * ldb + kt + lk);
        As[lk + 0][lm] = av.x; As[lk + 1][lm] = av.y; As[lk + 2][lm] = av.z; As[lk + 3][lm] = av.w;
        Bs[lk + 0][lm] = bv.x; Bs[lk + 1][lm] = bv.y; Bs[lk + 2][lm] = bv.z; Bs[lk + 3][lm] = bv.w;
        __syncthreads();
#pragma unroll
        for (int kk = 0; kk < BK; kk++) {
            float4 a = *reinterpret_cast<const float4*>(&As[kk][ty * 4]);
            float4 b = *reinterpret_cast<const float4*>(&Bs[kk][tx * 4]);
            acc[0][0] += a.x * b.x; acc[0][1] += a.x * b.y; acc[0][2] += a.x * b.z; acc[0][3] += a.x * b.w;
            acc[1][0] += a.y * b.x; acc[1][1] += a.y * b.y; acc[1][2] += a.y * b.z; acc[1][3] += a.y * b.w;
            acc[2][0] += a.z * b.x; acc[2][1] += a.z * b.y; acc[2][2] += a.z * b.z; acc[2][3] += a.z * b.w;
            acc[3][0] += a.w * b.x; acc[3][1] += a.w * b.y; acc[3][2] += a.w * b.z; acc[3][3] += a.w * b.w;
        }
        __syncthreads();
    }

#pragma unroll
    for (int i = 0; i < 4; i++) {
        const int m = row0 + ty * 4 + i;
#pragma unroll
        for (int j = 0; j < 4; j++) {
            const int n = col0 + tx * 4 + j;
            float v = acc[i][j] * scale;
            if (bias) v += bias[n];
            C[(long long)m * ldc + n] = v;
        }
    }
}

// C[m,n] = sum_k A[m,k]*B[k,n]  (A: K contiguous per row; B: N contiguous per row)
__global__ __launch_bounds__(256) void gemm_nn(
    const float* __restrict__ A, const float* __restrict__ Bm,
    float* __restrict__ C,
    int M, int N, int K, int lda, int ldb, int ldc,
    long long sAb, long long sAh, long long sBb, long long sBh,
    long long sCb, long long sCh, int Hdim)
{
    __shared__ float As[BK][BM + 4];
    __shared__ float Bs[BK][BN + 4];

    const int bz = blockIdx.z;
    const int bi = bz / Hdim, hi = bz % Hdim;
    A  += (long long)bi * sAb + (long long)hi * sAh;
    Bm += (long long)bi * sBb + (long long)hi * sBh;
    C  += (long long)bi * sCb + (long long)hi * sCh;

    const int tid = threadIdx.x;
    const int tx = tid & 15, ty = tid >> 4;
    const int row0 = blockIdx.y * BM;
    const int col0 = blockIdx.x * BN;

    float acc[4][4];
#pragma unroll
    for (int i = 0; i < 4; i++)
#pragma unroll
        for (int j = 0; j < 4; j++) acc[i][j] = 0.0f;

    const int lm = tid >> 2;          // 0..63 (A rows)
    const int lk = (tid & 3) * 4;     // A k-offset
    const int bk = tid >> 4;          // 0..15 (B rows = k)
    const int bn = (tid & 15) * 4;    // B n-offset

    for (int kt = 0; kt < K; kt += BK) {
        float4 av = *reinterpret_cast<const float4*>(A  + (long long)(row0 + lm) * lda + kt + lk);
        float4 bv = *reinterpret_cast<const float4*>(Bm + (long long)(kt + bk) * ldb + col0 + bn);
        As[lk + 0][lm] = av.x; As[lk + 1][lm] = av.y; As[lk + 2][lm] = av.z; As[lk + 3][lm] = av.w;
        *reinterpret_cast<float4*>(&Bs[bk][bn]) = bv;
        __syncthreads();
#pragma unroll
        for (int kk = 0; kk < BK; kk++) {
            float4 a = *reinterpret_cast<const float4*>(&As[kk][ty * 4]);
            float4 b = *reinterpret_cast<const float4*>(&Bs[kk][tx * 4]);
            acc[0][0] += a.x * b.x; acc[0][1] += a.x * b.y; acc[0][2] += a.x * b.z; acc[0][3] += a.x * b.w;
            acc[1][0] += a.y * b.x; acc[1][1] += a.y * b.y; acc[1][2] += a.y * b.z; acc[1][3] += a.y * b.w;
            acc[2][0] += a.z * b.x; acc[2][1] += a.z * b.y; acc[2][2] += a.z * b.z; acc[2][3] += a.z * b.w;
            acc[3][0] += a.w * b.x; acc[3][1] += a.w * b.y; acc[3][2] += a.w * b.z; acc[3][3] += a.w * b.w;
        }
        __syncthreads();
    }

#pragma unroll
    for (int i = 0; i < 4; i++) {
        const int m = row0 + ty * 4 + i;
#pragma unroll
        for (int j = 0; j < 4; j++) {
            const int n = col0 + tx * 4 + j;
            C[(long long)m * ldc + n] = acc[i][j];
        }
    }
}

// In-place row softmax; one block per row of length ncols.
__global__ __launch_bounds__(256) void softmax_rows(float* __restrict__ att, int ncols)
{
    float* p = att + (long long)blockIdx.x * ncols;
    const int tid = threadIdx.x;
    __shared__ float red[256];

    float m = -1e30f;
    for (int c = tid; c < ncols; c += 256) m = fmaxf(m, p[c]);
    red[tid] = m; __syncthreads();
    for (int s = 128; s > 0; s >>= 1) { if (tid < s) red[tid] = fmaxf(red[tid], red[tid + s]); __syncthreads(); }
    m = red[0]; __syncthreads();

    float sum = 0.0f;
    for (int c = tid; c < ncols; c += 256) {
        float e = __expf(p[c] - m);
        p[c] = e;
        sum += e;
    }
    red[tid] = sum; __syncthreads();
    for (int s = 128; s > 0; s >>= 1) { if (tid < s) red[tid] += red[tid + s]; __syncthreads(); }
    const float inv = 1.0f / red[0];
    for (int c = tid; c < ncols; c += 256) p[c] *= inv;
}

extern "C" void kernel_launch(void* const* d_in, const int* in_sizes, int n_in,
                              void* d_out, int out_size)
{
    const float* q  = (const float*)d_in[0];
    const float* k  = (const float*)d_in[1];
    const float* v  = (const float*)d_in[2];
    const float* Wq = (const float*)d_in[3];
    const float* bq = (const float*)d_in[4];
    const float* Wk = (const float*)d_in[5];
    const float* bk = (const float*)d_in[6];
    const float* Wv = (const float*)d_in[7];
    const float* bv = (const float*)d_in[8];
    const float* Wo = (const float*)d_in[9];
    const float* bo = (const float*)d_in[10];
    float* out = (float*)d_out;

    float *qp, *kp, *vp, *attn;
    cudaGetSymbolAddress((void**)&qp, g_q);
    cudaGetSymbolAddress((void**)&kp, g_k);
    cudaGetSymbolAddress((void**)&vp, g_v);
    if ((long long)out_size >= BSD_LL + ATTN_LL) {
        attn = out + BSD_LL;                 // tuple output: (out, attn)
    } else {
        cudaGetSymbolAddress((void**)&attn, g_attn_fallback);
    }
    float* ctx = qp;  // reuse g_q after logits are done

    dim3 blk(256);
    const float inv_sqrt_dk = 0.125f; // 1/sqrt(64)

    // 1) Projections: [8192,1024] = X[8192,1024] @ W[1024,1024]^T + b
    {
        dim3 grid(D_ / BN, (int)(BS_LL / BM), 1);
        gemm_nt<<<grid, blk>>>(q, Wq, bq, qp, (int)BS_LL, D_, D_, D_, D_, D_,
                               0, 0, 0, 0, 0, 0, 1, 1.0f);
        gemm_nt<<<grid, blk>>>(k, Wk, bk, kp, (int)BS_LL, D_, D_, D_, D_, D_,
                               0, 0, 0, 0, 0, 0, 1, 1.0f);
        gemm_nt<<<grid, blk>>>(v, Wv, bv, vp, (int)BS_LL, D_, D_, D_, D_, D_,
                               0, 0, 0, 0, 0, 0, 1, 1.0f);
    }

    // 2) Logits: attn[b,h,i,j] = scale * dot(Qp[b,i,h*64:], Kp[b,j,h*64:])
    {
        dim3 grid(S_ / BN, S_ / BM, B_ * H_);
        gemm_nt<<<grid, blk>>>(qp, kp, nullptr, attn, S_, S_, DK_, D_, D_, S_,
                               (long long)S_ * D_, DK_,
                               (long long)S_ * D_, DK_,
                               (long long)H_ * S_ * S_, (long long)S_ * S_,
                               H_, inv_sqrt_dk);
    }

    // 3) Softmax over last dim, in place
    {
        dim3 grid((unsigned)(B_ * H_ * S_));
        softmax_rows<<<grid, blk>>>(attn, S_);
    }

    // 4) Ctx: ctx[b,i,h*64+d] = sum_j attn[b,h,i,j] * Vp[b,j,h*64+d]
    {
        dim3 grid(DK_ / BN, S_ / BM, B_ * H_);
        gemm_nn<<<grid, blk>>>(attn, vp, ctx, S_, DK_, S_, S_, D_, D_,
                               (long long)H_ * S_ * S_, (long long)S_ * S_,
                               (long long)S_ * D_, DK_,
                               (long long)S_ * D_, DK_,
                               H_);
    }

    // 5) Output projection: out = ctx @ Wo^T + bo
    {
        dim3 grid(D_ / BN, (int)(BS_LL / BM), 1);
        gemm_nt<<<grid, blk>>>(ctx, Wo, bo, out, (int)BS_LL, D_, D_, D_, D_, D_,
                               0, 0, 0, 0, 0, 0, 1, 1.0f);
    }
}

// round 3
// speedup vs baseline: 1.1351x; 1.1351x over previous
#include <cuda_runtime.h>

// Problem constants
#define B_  4
#define S_  2048
#define D_  1024
#define H_  16
#define DK_ 64

static const long long BS_LL   = (long long)B_ * S_;           // 8192
static const long long BSD_LL  = (long long)B_ * S_ * D_;      // 8388608
static const long long ATTN_LL = (long long)B_ * H_ * S_ * S_; // 268435456

// Scratch (allocation-free rule: __device__ globals)
__device__ float g_q[(size_t)BSD_LL];   // Q projected; reused as Ctx later
__device__ float g_k[(size_t)BSD_LL];
__device__ float g_v[(size_t)BSD_LL];
__device__ float g_attn_fallback[(size_t)ATTN_LL];

// ---------------------------------------------------------------------------
// Templated register-tiled GEMM.
//   NT mode (B_KCONTIG=true):  C[m,n] = scale*sum_k A[m,k]*B[n,k] (+bias[n])
//   NN mode (B_KCONTIG=false): C[m,n] = scale*sum_k A[m,k]*B[k,n] (+bias[n])
// A rows always K-contiguous. Batched over z = b*Hdim + h.
// ---------------------------------------------------------------------------
template <int BM, int BN, int BK, int TM, int TN, bool B_KCONTIG>
__global__ __launch_bounds__((BM / TM) * (BN / TN)) void gemm_rt(
    const float* __restrict__ A, const float* __restrict__ Bm,
    const float* __restrict__ bias, float* __restrict__ C,
    int K, int lda, int ldb, int ldc,
    long long sAb, long long sAh, long long sBb, long long sBh,
    long long sCb, long long sCh, int Hdim, float scale)
{
    constexpr int NT = (BM / TM) * (BN / TN);
    constexpr int NX = BN / TN;

    __shared__ float As[BK][BM + 4];
    __shared__ float Bs[BK][BN + 4];

    const int bz = blockIdx.z;
    const int bi = bz / Hdim, hi = bz % Hdim;
    A  += (long long)bi * sAb + (long long)hi * sAh;
    Bm += (long long)bi * sBb + (long long)hi * sBh;
    C  += (long long)bi * sCb + (long long)hi * sCh;

    const int tid = threadIdx.x;
    const int tx = tid % NX, ty = tid / NX;
    const int row0 = blockIdx.y * BM;
    const int col0 = blockIdx.x * BN;

    float acc[TM][TN];
#pragma unroll
    for (int i = 0; i < TM; i++)
#pragma unroll
        for (int j = 0; j < TN; j++) acc[i][j] = 0.0f;

    for (int kt = 0; kt < K; kt += BK) {
        // Load A tile (K-contiguous rows) into As[k][m]
#pragma unroll
        for (int idx = tid; idx < BM * BK / 4; idx += NT) {
            const int r  = idx / (BK / 4);
            const int kc = (idx % (BK / 4)) * 4;
            float4 v = *reinterpret_cast<const float4*>(
                A + (long long)(row0 + r) * lda + kt + kc);
            As[kc + 0][r] = v.x; As[kc + 1][r] = v.y;
            As[kc + 2][r] = v.z; As[kc + 3][r] = v.w;
        }
        // Load B tile
        if (B_KCONTIG) {
#pragma unroll
            for (int idx = tid; idx < BN * BK / 4; idx += NT) {
                const int r  = idx / (BK / 4);
                const int kc = (idx % (BK / 4)) * 4;
                float4 v = *reinterpret_cast<const float4*>(
                    Bm + (long long)(col0 + r) * ldb + kt + kc);
                Bs[kc + 0][r] = v.x; Bs[kc + 1][r] = v.y;
                Bs[kc + 2][r] = v.z; Bs[kc + 3][r] = v.w;
            }
        } else {
#pragma unroll
            for (int idx = tid; idx < BK * BN / 4; idx += NT) {
                const int r  = idx / (BN / 4);
                const int nc = (idx % (BN / 4)) * 4;
                float4 v = *reinterpret_cast<const float4*>(
                    Bm + (long long)(kt + r) * ldb + col0 + nc);
                *reinterpret_cast<float4*>(&Bs[r][nc]) = v;
            }
        }
        __syncthreads();

#pragma unroll
        for (int kk = 0; kk < BK; kk++) {
            float a[TM], b[TN];
#pragma unroll
            for (int i = 0; i < TM; i += 4)
                *reinterpret_cast<float4*>(&a[i]) =
                    *reinterpret_cast<const float4*>(&As[kk][ty * TM + i]);
#pragma unroll
            for (int j = 0; j < TN; j += 4)
                *reinterpret_cast<float4*>(&b[j]) =
                    *reinterpret_cast<const float4*>(&Bs[kk][tx * TN + j]);
#pragma unroll
            for (int i = 0; i < TM; i++)
#pragma unroll
                for (int j = 0; j < TN; j++)
                    acc[i][j] += a[i] * b[j];
        }
        __syncthreads();
    }

    // Epilogue: scale, bias, vectorized store
#pragma unroll
    for (int i = 0; i < TM; i++) {
        const int m = row0 + ty * TM + i;
#pragma unroll
        for (int j = 0; j < TN; j += 4) {
            const int n = col0 + tx * TN + j;
            float4 v;
            v.x = acc[i][j + 0] * scale;
            v.y = acc[i][j + 1] * scale;
            v.z = acc[i][j + 2] * scale;
            v.w = acc[i][j + 3] * scale;
            if (bias) {
                v.x += __ldg(bias + n + 0); v.y += __ldg(bias + n + 1);
                v.z += __ldg(bias + n + 2); v.w += __ldg(bias + n + 3);
            }
            *reinterpret_cast<float4*>(C + (long long)m * ldc + n) = v;
        }
    }
}

// ---------------------------------------------------------------------------
// Row softmax, row length 2048, entirely register-resident.
// 256 threads/block, 8 floats/thread (two float4 strided loads).
// ---------------------------------------------------------------------------
__global__ __launch_bounds__(256) void softmax_rows2048(float* __restrict__ att)
{
    float4* p4 = reinterpret_cast<float4*>(att + (long long)blockIdx.x * 2048);
    const int tid = threadIdx.x;
    __shared__ float red[32];

    float4 v0 = p4[tid];
    float4 v1 = p4[tid + 256];

    // --- max ---
    float m = fmaxf(fmaxf(fmaxf(v0.x, v0.y), fmaxf(v0.z, v0.w)),
                    fmaxf(fmaxf(v1.x, v1.y), fmaxf(v1.z, v1.w)));
#pragma unroll
    for (int o = 16; o > 0; o >>= 1) m = fmaxf(m, __shfl_xor_sync(0xffffffffu, m, o));
    if ((tid & 31) == 0) red[tid >> 5] = m;
    __syncthreads();
    if (tid < 32) {
        float t = red[tid & 7];
#pragma unroll
        for (int o = 4; o > 0; o >>= 1) t = fmaxf(t, __shfl_xor_sync(0xffffffffu, t, o));
        red[tid & 7] = t;  // all 8 slots now hold global max
    }
    __syncthreads();
    m = red[0];

    // --- exp + sum ---
    v0.x = __expf(v0.x - m); v0.y = __expf(v0.y - m);
    v0.z = __expf(v0.z - m); v0.w = __expf(v0.w - m);
    v1.x = __expf(v1.x - m); v1.y = __expf(v1.y - m);
    v1.z = __expf(v1.z - m); v1.w = __expf(v1.w - m);
    float s = v0.x + v0.y + v0.z + v0.w + v1.x + v1.y + v1.z + v1.w;
#pragma unroll
    for (int o = 16; o > 0; o >>= 1) s += __shfl_xor_sync(0xffffffffu, s, o);
    __syncthreads();
    if ((tid & 31) == 0) red[tid >> 5] = s;
    __syncthreads();
    if (tid < 32) {
        float t = red[tid & 7];
#pragma unroll
        for (int o = 4; o > 0; o >>= 1) t += __shfl_xor_sync(0xffffffffu, t, o);
        red[tid & 7] = t;
    }
    __syncthreads();
    const float inv = 1.0f / red[0];

    v0.x *= inv; v0.y *= inv; v0.z *= inv; v0.w *= inv;
    v1.x *= inv; v1.y *= inv; v1.z *= inv; v1.w *= inv;
    p4[tid] = v0;
    p4[tid + 256] = v1;
}

extern "C" void kernel_launch(void* const* d_in, const int* in_sizes, int n_in,
                              void* d_out, int out_size)
{
    const float* q  = (const float*)d_in[0];
    const float* k  = (const float*)d_in[1];
    const float* v  = (const float*)d_in[2];
    const float* Wq = (const float*)d_in[3];
    const float* bq = (const float*)d_in[4];
    const float* Wk = (const float*)d_in[5];
    const float* bk = (const float*)d_in[6];
    const float* Wv = (const float*)d_in[7];
    const float* bv = (const float*)d_in[8];
    const float* Wo = (const float*)d_in[9];
    const float* bo = (const float*)d_in[10];
    float* out = (float*)d_out;

    float *qp, *kp, *vp, *attn;
    cudaGetSymbolAddress((void**)&qp, g_q);
    cudaGetSymbolAddress((void**)&kp, g_k);
    cudaGetSymbolAddress((void**)&vp, g_v);
    if ((long long)out_size >= BSD_LL + ATTN_LL) {
        attn = out + BSD_LL;                 // tuple output: (out, attn)
    } else {
        cudaGetSymbolAddress((void**)&attn, g_attn_fallback);
    }
    float* ctx = qp;  // reuse g_q after logits are done

    const float inv_sqrt_dk = 0.125f; // 1/sqrt(64)

    // 1) Projections: [8192,1024] = X @ W^T + b   (BM=BN=128, 256 thr)
    {
        dim3 grid(D_ / 128, (int)(BS_LL / 128), 1);
        gemm_rt<128,128,16,8,8,true><<<grid, 256>>>(
            q, Wq, bq, qp, D_, D_, D_, D_, 0,0,0,0,0,0, 1, 1.0f);
        gemm_rt<128,128,16,8,8,true><<<grid, 256>>>(
            k, Wk, bk, kp, D_, D_, D_, D_, 0,0,0,0,0,0, 1, 1.0f);
        gemm_rt<128,128,16,8,8,true><<<grid, 256>>>(
            v, Wv, bv, vp, D_, D_, D_, D_, 0,0,0,0,0,0, 1, 1.0f);
    }

    // 2) Logits: attn[b,h,i,j] = scale * dot(Qp[b,i,h*64:], Kp[b,j,h*64:])
    {
        dim3 grid(S_ / 128, S_ / 128, B_ * H_);
        gemm_rt<128,128,16,8,8,true><<<grid, 256>>>(
            qp, kp, nullptr, attn, DK_, D_, D_, S_,
            (long long)S_ * D_, DK_,
            (long long)S_ * D_, DK_,
            (long long)H_ * S_ * S_, (long long)S_ * S_,
            H_, inv_sqrt_dk);
    }

    // 3) Softmax over last dim, in place, register-resident rows
    {
        softmax_rows2048<<<(unsigned)(B_ * H_ * S_), 256>>>(attn);
    }

    // 4) Ctx: ctx[b,i,h*64+d] = sum_j attn[b,h,i,j] * Vp[b,j,h*64+d]
    //    M=2048, N=64, K=2048  (BM=128, BN=64, 128 thr)
    {
        dim3 grid(DK_ / 64, S_ / 128, B_ * H_);
        gemm_rt<128,64,16,8,8,false><<<grid, 128>>>(
            attn, vp, nullptr, ctx, S_, S_, D_, D_,
            (long long)H_ * S_ * S_, (long long)S_ * S_,
            (long long)S_ * D_, DK_,
            (long long)S_ * D_, DK_,
            H_, 1.0f);
    }

    // 5) Output projection: out = ctx @ Wo^T + bo
    {
        dim3 grid(D_ / 128, (int)(BS_LL / 128), 1);
        gemm_rt<128,128,16,8,8,true><<<grid, 256>>>(
            ctx, Wo, bo, out, D_, D_, D_, D_, 0,0,0,0,0,0, 1, 1.0f);
    }
}

// round 5
// speedup vs baseline: 2.1640x; 1.9065x over previous
#include <cuda_runtime.h>
#include <cuda_bf16.h>
#include <cstdint>

// Problem constants
#define B_  4
#define S_  2048
#define D_  1024
#define H_  16
#define DK_ 64

static const long long BS_LL   = (long long)B_ * S_;           // 8192
static const long long BSD_LL  = (long long)B_ * S_ * D_;      // 8388608
static const long long ATTN_LL = (long long)B_ * H_ * S_ * S_; // 268435456

// Scratch (allocation-free rule: __device__ globals)
__device__ float g_q[(size_t)BSD_LL];   // Q projected; reused as Ctx later
__device__ float g_k[(size_t)BSD_LL];
__device__ float g_v[(size_t)BSD_LL];   // V projected, stored transposed [B][H][DK][S]
__device__ float g_attn_fallback[(size_t)ATTN_LL];

__device__ __forceinline__ uint32_t smem_u32(const void* p) {
    uint32_t a;
    asm("{ .reg .u64 t; cvta.to.shared.u64 t, %1; cvt.u32.u64 %0, t; }" : "=r"(a) : "l"(p));
    return a;
}

__device__ __forceinline__ void ldmx4(uint32_t* r, uint32_t addr) {
    asm volatile("ldmatrix.sync.aligned.m8n8.x4.shared.b16 {%0,%1,%2,%3}, [%4];"
                 : "=r"(r[0]), "=r"(r[1]), "=r"(r[2]), "=r"(r[3]) : "r"(addr));
}
__device__ __forceinline__ void ldmx2(uint32_t* r, uint32_t addr) {
    asm volatile("ldmatrix.sync.aligned.m8n8.x2.shared.b16 {%0,%1}, [%2];"
                 : "=r"(r[0]), "=r"(r[1]) : "r"(addr));
}
__device__ __forceinline__ void mma16816(float* c, const uint32_t* a, const uint32_t* b) {
    asm volatile(
        "mma.sync.aligned.m16n8k16.row.col.f32.bf16.bf16.f32 "
        "{%0,%1,%2,%3}, {%4,%5,%6,%7}, {%8,%9}, {%0,%1,%2,%3};"
        : "+f"(c[0]), "+f"(c[1]), "+f"(c[2]), "+f"(c[3])
        : "r"(a[0]), "r"(a[1]), "r"(a[2]), "r"(a[3]), "r"(b[0]), "r"(b[1]));
}

// Split a float4 into packed bf16 hi (truncation, exact) and lo (remainder).
__device__ __forceinline__ void split4(const float4& v, uint2& hi, uint2& lo) {
    uint32_t ux = __float_as_uint(v.x), uy = __float_as_uint(v.y);
    uint32_t uz = __float_as_uint(v.z), uw = __float_as_uint(v.w);
    hi.x = (ux >> 16) | (uy & 0xFFFF0000u);
    hi.y = (uz >> 16) | (uw & 0xFFFF0000u);
    float lx = v.x - __uint_as_float(ux & 0xFFFF0000u);
    float ly = v.y - __uint_as_float(uy & 0xFFFF0000u);
    float lz = v.z - __uint_as_float(uz & 0xFFFF0000u);
    float lw = v.w - __uint_as_float(uw & 0xFFFF0000u);
    __nv_bfloat162 l0 = __floats2bfloat162_rn(lx, ly);
    __nv_bfloat162 l1 = __floats2bfloat162_rn(lz, lw);
    lo.x = *reinterpret_cast<uint32_t*>(&l0);
    lo.y = *reinterpret_cast<uint32_t*>(&l1);
}

// ---------------------------------------------------------------------------
// bf16-split tensor-core GEMM (mma.sync, sm_80+ portable):
//   C[m,n] = scale * sum_k A[m,k]*B[n,k] (+ bias[n])
// A, B rows K-contiguous. Batched over z = bi*Hdim + hi.
// BM=128, BN in {128,64}, BK=32, 256 threads (8 warps).
// transV: store C transposed per-head ([B][H][DK][S]) for the V projection.
// ---------------------------------------------------------------------------
template <int BN>
__global__ __launch_bounds__(256) void gemm_mma(
    const float* __restrict__ A, const float* __restrict__ Bm,
    const float* __restrict__ bias, float* __restrict__ C,
    int K, int lda, int ldb, int ldc,
    long long sAb, long long sAh, long long sBb, long long sBh,
    long long sCb, long long sCh, int Hdim, float scale, int transV)
{
    constexpr int BM = 128, BK = 32;
    constexpr int SK = 40;                       // smem row stride (halves), conflict-free
    constexpr int NB4 = BN * BK / 4 / 256;       // B float4s per thread (4 or 2)
    constexpr int WGM = (BN == 128) ? 2 : 4;     // warp grid
    constexpr int WGN = (BN == 128) ? 4 : 2;
    constexpr int WM = BM / WGM, WN = BN / WGN;
    constexpr int MF = WM / 16, NF = WN / 8;

    __shared__ __nv_bfloat16 Ah[BM * SK], Al[BM * SK];
    __shared__ __nv_bfloat16 Bh[BN * SK], Bl[BN * SK];

    const int bz = blockIdx.z;
    const int bi = bz / Hdim, hi2 = bz % Hdim;
    A  += (long long)bi * sAb + (long long)hi2 * sAh;
    Bm += (long long)bi * sBb + (long long)hi2 * sBh;
    C  += (long long)bi * sCb + (long long)hi2 * sCh;

    const int tid = threadIdx.x;
    const int wid = tid >> 5, lane = tid & 31;
    const int wm = (BN == 128) ? (wid >> 2) : (wid >> 1);
    const int wn = (BN == 128) ? (wid & 3) : (wid & 1);
    const int row0 = blockIdx.y * BM;
    const int col0 = blockIdx.x * BN;

    float acc[MF][NF][4];
#pragma unroll
    for (int i = 0; i < MF; i++)
#pragma unroll
        for (int j = 0; j < NF; j++)
#pragma unroll
            for (int c = 0; c < 4; c++) acc[i][j][c] = 0.0f;

    // ldmatrix base addresses (per-thread row assignments)
    const uint32_t a_base = smem_u32(Ah), al_base = smem_u32(Al);
    const uint32_t b_base = smem_u32(Bh), bl_base = smem_u32(Bl);
    const int a_row = wm * WM + (lane & 15);        // + mf*16
    const int a_kof = 8 * (lane >> 4);
    const int b_row = wn * WN + (lane & 7);         // + nf*8
    const int b_kof = 8 * ((lane >> 3) & 1);

    // Prefetch first k-tile
    float4 a4[4], b4[NB4];
#pragma unroll
    for (int j = 0; j < 4; j++) {
        int f = tid + j * 256, r = f >> 3, c = f & 7;
        a4[j] = *reinterpret_cast<const float4*>(A + (long long)(row0 + r) * lda + c * 4);
    }
#pragma unroll
    for (int j = 0; j < NB4; j++) {
        int f = tid + j * 256, r = f >> 3, c = f & 7;
        b4[j] = *reinterpret_cast<const float4*>(Bm + (long long)(col0 + r) * ldb + c * 4);
    }

    for (int kt = 0; kt < K; kt += BK) {
        // Split + store to smem
#pragma unroll
        for (int j = 0; j < 4; j++) {
            int f = tid + j * 256, r = f >> 3, c = f & 7;
            uint2 h, l; split4(a4[j], h, l);
            *reinterpret_cast<uint2*>(&Ah[r * SK + c * 4]) = h;
            *reinterpret_cast<uint2*>(&Al[r * SK + c * 4]) = l;
        }
#pragma unroll
        for (int j = 0; j < NB4; j++) {
            int f = tid + j * 256, r = f >> 3, c = f & 7;
            uint2 h, l; split4(b4[j], h, l);
            *reinterpret_cast<uint2*>(&Bh[r * SK + c * 4]) = h;
            *reinterpret_cast<uint2*>(&Bl[r * SK + c * 4]) = l;
        }
        __syncthreads();

        // Prefetch next k-tile (overlaps with MMA below)
        if (kt + BK < K) {
#pragma unroll
            for (int j = 0; j < 4; j++) {
                int f = tid + j * 256, r = f >> 3, c = f & 7;
                a4[j] = *reinterpret_cast<const float4*>(
                    A + (long long)(row0 + r) * lda + kt + BK + c * 4);
            }
#pragma unroll
            for (int j = 0; j < NB4; j++) {
                int f = tid + j * 256, r = f >> 3, c = f & 7;
                b4[j] = *reinterpret_cast<const float4*>(
                    Bm + (long long)(col0 + r) * ldb + kt + BK + c * 4);
            }
        }

        // Compute: 2 k16 steps
#pragma unroll
        for (int ks = 0; ks < 2; ks++) {
            const int k16 = ks * 16;
            uint32_t bh[NF][2], bl[NF][2];
#pragma unroll
            for (int nf = 0; nf < NF; nf++) {
                uint32_t off = ((b_row + nf * 8) * SK + k16 + b_kof) * 2;
                ldmx2(bh[nf], b_base + off);
                ldmx2(bl[nf], bl_base + off);
            }
#pragma unroll
            for (int mf = 0; mf < MF; mf++) {
                uint32_t ah[4], al[4];
                uint32_t off = ((a_row + mf * 16) * SK + k16 + a_kof) * 2;
                ldmx4(ah, a_base + off);
                ldmx4(al, al_base + off);
#pragma unroll
                for (int nf = 0; nf < NF; nf++) {
                    mma16816(acc[mf][nf], ah, bh[nf]);   // hi*hi
                    mma16816(acc[mf][nf], ah, bl[nf]);   // hi*lo
                    mma16816(acc[mf][nf], al, bh[nf]);   // lo*hi
                }
            }
        }
        __syncthreads();
    }

    // Epilogue
#pragma unroll
    for (int mf = 0; mf < MF; mf++) {
#pragma unroll
        for (int nf = 0; nf < NF; nf++) {
            const int rg = row0 + wm * WM + mf * 16 + (lane >> 2);
            const int cg = col0 + wn * WN + nf * 8 + 2 * (lane & 3);
            if (!transV) {
                float2 v0, v1;
                v0.x = acc[mf][nf][0] * scale; v0.y = acc[mf][nf][1] * scale;
                v1.x = acc[mf][nf][2] * scale; v1.y = acc[mf][nf][3] * scale;
                if (bias) {
                    float bx = __ldg(bias + cg), by = __ldg(bias + cg + 1);
                    v0.x += bx; v0.y += by; v1.x += bx; v1.y += by;
                }
                *reinterpret_cast<float2*>(C + (long long)rg * ldc + cg) = v0;
                *reinterpret_cast<float2*>(C + (long long)(rg + 8) * ldc + cg) = v1;
            } else {
                // transposed per-head store: C[((b*H + h)*DK + d)*S + i]
#pragma unroll
                for (int e = 0; e < 4; e++) {
                    const int r = rg + (e >> 1) * 8;
                    const int n = cg + (e & 1);
                    float v = acc[mf][nf][e] * scale;
                    if (bias) v += __ldg(bias + n);
                    const int b = r >> 11, ii = r & 2047;
                    const long long idx =
                        (((long long)(b * H_ + (n >> 6)) * DK_ + (n & 63)) << 11) + ii;
                    C[idx] = v;
                }
            }
        }
    }
}

// ---------------------------------------------------------------------------
// Row softmax, row length 2048, register-resident.
// ---------------------------------------------------------------------------
__global__ __launch_bounds__(256) void softmax_rows2048(float* __restrict__ att)
{
    float4* p4 = reinterpret_cast<float4*>(att + (long long)blockIdx.x * 2048);
    const int tid = threadIdx.x;
    __shared__ float red[32];

    float4 v0 = p4[tid];
    float4 v1 = p4[tid + 256];

    float m = fmaxf(fmaxf(fmaxf(v0.x, v0.y), fmaxf(v0.z, v0.w)),
                    fmaxf(fmaxf(v1.x, v1.y), fmaxf(v1.z, v1.w)));
#pragma unroll
    for (int o = 16; o > 0; o >>= 1) m = fmaxf(m, __shfl_xor_sync(0xffffffffu, m, o));
    if ((tid & 31) == 0) red[tid >> 5] = m;
    __syncthreads();
    if (tid < 32) {
        float t = red[tid & 7];
#pragma unroll
        for (int o = 4; o > 0; o >>= 1) t = fmaxf(t, __shfl_xor_sync(0xffffffffu, t, o));
        red[tid & 7] = t;
    }
    __syncthreads();
    m = red[0];

    v0.x = __expf(v0.x - m); v0.y = __expf(v0.y - m);
    v0.z = __expf(v0.z - m); v0.w = __expf(v0.w - m);
    v1.x = __expf(v1.x - m); v1.y = __expf(v1.y - m);
    v1.z = __expf(v1.z - m); v1.w = __expf(v1.w - m);
    float s = v0.x + v0.y + v0.z + v0.w + v1.x + v1.y + v1.z + v1.w;
#pragma unroll
    for (int o = 16; o > 0; o >>= 1) s += __shfl_xor_sync(0xffffffffu, s, o);
    __syncthreads();
    if ((tid & 31) == 0) red[tid >> 5] = s;
    __syncthreads();
    if (tid < 32) {
        float t = red[tid & 7];
#pragma unroll
        for (int o = 4; o > 0; o >>= 1) t += __shfl_xor_sync(0xffffffffu, t, o);
        red[tid & 7] = t;
    }
    __syncthreads();
    const float inv = 1.0f / red[0];

    v0.x *= inv; v0.y *= inv; v0.z *= inv; v0.w *= inv;
    v1.x *= inv; v1.y *= inv; v1.z *= inv; v1.w *= inv;
    p4[tid] = v0;
    p4[tid + 256] = v1;
}

extern "C" void kernel_launch(void* const* d_in, const int* in_sizes, int n_in,
                              void* d_out, int out_size)
{
    const float* q  = (const float*)d_in[0];
    const float* k  = (const float*)d_in[1];
    const float* v  = (const float*)d_in[2];
    const float* Wq = (const float*)d_in[3];
    const float* bq = (const float*)d_in[4];
    const float* Wk = (const float*)d_in[5];
    const float* bk = (const float*)d_in[6];
    const float* Wv = (const float*)d_in[7];
    const float* bv = (const float*)d_in[8];
    const float* Wo = (const float*)d_in[9];
    const float* bo = (const float*)d_in[10];
    float* out = (float*)d_out;

    float *qp, *kp, *vt, *attn;
    cudaGetSymbolAddress((void**)&qp, g_q);
    cudaGetSymbolAddress((void**)&kp, g_k);
    cudaGetSymbolAddress((void**)&vt, g_v);
    if ((long long)out_size >= BSD_LL + ATTN_LL) {
        attn = out + BSD_LL;                 // tuple output: (out, attn)
    } else {
        cudaGetSymbolAddress((void**)&attn, g_attn_fallback);
    }
    float* ctx = qp;  // reuse g_q after logits are done

    const float inv_sqrt_dk = 0.125f; // 1/sqrt(64)

    // 1) Projections: [8192,1024] = X @ W^T + b
    {
        dim3 grid(D_ / 128, (int)(BS_LL / 128), 1);
        gemm_mma<128><<<grid, 256>>>(
            q, Wq, bq, qp, D_, D_, D_, D_, 0,0,0,0,0,0, 1, 1.0f, 0);
        gemm_mma<128><<<grid, 256>>>(
            k, Wk, bk, kp, D_, D_, D_, D_, 0,0,0,0,0,0, 1, 1.0f, 0);
        gemm_mma<128><<<grid, 256>>>(
            v, Wv, bv, vt, D_, D_, D_, D_, 0,0,0,0,0,0, 1, 1.0f, 1);  // transposed store
    }

    // 2) Logits: attn[b,h,i,j] = scale * dot(Qp[b,i,h*64:], Kp[b,j,h*64:])
    {
        dim3 grid(S_ / 128, S_ / 128, B_ * H_);
        gemm_mma<128><<<grid, 256>>>(
            qp, kp, nullptr, attn, DK_, D_, D_, S_,
            (long long)S_ * D_, DK_,
            (long long)S_ * D_, DK_,
            (long long)H_ * S_ * S_, (long long)S_ * S_,
            H_, inv_sqrt_dk, 0);
    }

    // 3) Softmax over last dim, in place
    softmax_rows2048<<<(unsigned)(B_ * H_ * S_), 256>>>(attn);

    // 4) Ctx: ctx[b,i,h*64+d] = sum_j attn[b,h,i,j] * Vt[b,h,d,j]
    {
        dim3 grid(1, S_ / 128, B_ * H_);
        gemm_mma<64><<<grid, 256>>>(
            attn, vt, nullptr, ctx, S_, S_, S_, D_,
            (long long)H_ * S_ * S_, (long long)S_ * S_,
            (long long)S_ * D_, (long long)DK_ * S_,
            (long long)S_ * D_, (long long)DK_,
            H_, 1.0f, 0);
    }

    // 5) Output projection: out = ctx @ Wo^T + bo
    {
        dim3 grid(D_ / 128, (int)(BS_LL / 128), 1);
        gemm_mma<128><<<grid, 256>>>(
            ctx, Wo, bo, out, D_, D_, D_, D_, 0,0,0,0,0,0, 1, 1.0f, 0);
    }
}

// round 6
// speedup vs baseline: 2.3625x; 1.0917x over previous
#include <cuda_runtime.h>
#include <cuda_bf16.h>
#include <cstdint>

// Problem constants
#define B_  4
#define S_  2048
#define D_  1024
#define H_  16
#define DK_ 64

static const long long BS_LL   = (long long)B_ * S_;           // 8192
static const long long BSD_LL  = (long long)B_ * S_ * D_;      // 8388608
static const long long ATTN_LL = (long long)B_ * H_ * S_ * S_; // 268435456

// Scratch (allocation-free rule: __device__ globals)
__device__ float g_q[(size_t)BSD_LL];   // Q projected; reused as Ctx later
__device__ float g_k[(size_t)BSD_LL];
__device__ float g_v[(size_t)BSD_LL];   // V projected, stored transposed [B][H][DK][S]
__device__ float g_attn_fallback[(size_t)ATTN_LL];

__device__ __forceinline__ uint32_t smem_u32(const void* p) {
    uint32_t a;
    asm("{ .reg .u64 t; cvta.to.shared.u64 t, %1; cvt.u32.u64 %0, t; }" : "=r"(a) : "l"(p));
    return a;
}

__device__ __forceinline__ void ldmx4(uint32_t* r, uint32_t addr) {
    asm volatile("ldmatrix.sync.aligned.m8n8.x4.shared.b16 {%0,%1,%2,%3}, [%4];"
                 : "=r"(r[0]), "=r"(r[1]), "=r"(r[2]), "=r"(r[3]) : "r"(addr));
}
__device__ __forceinline__ void ldmx2(uint32_t* r, uint32_t addr) {
    asm volatile("ldmatrix.sync.aligned.m8n8.x2.shared.b16 {%0,%1}, [%2];"
                 : "=r"(r[0]), "=r"(r[1]) : "r"(addr));
}
__device__ __forceinline__ void mma16816(float* c, const uint32_t* a, const uint32_t* b) {
    asm volatile(
        "mma.sync.aligned.m16n8k16.row.col.f32.bf16.bf16.f32 "
        "{%0,%1,%2,%3}, {%4,%5,%6,%7}, {%8,%9}, {%0,%1,%2,%3};"
        : "+f"(c[0]), "+f"(c[1]), "+f"(c[2]), "+f"(c[3])
        : "r"(a[0]), "r"(a[1]), "r"(a[2]), "r"(a[3]), "r"(b[0]), "r"(b[1]));
}
__device__ __forceinline__ void sts64(uint32_t addr, uint2 v) {
    asm volatile("st.shared.v2.b32 [%0], {%1, %2};" :: "r"(addr), "r"(v.x), "r"(v.y) : "memory");
}

// Split a float4 into packed bf16 hi (truncation, exact) and lo (remainder).
__device__ __forceinline__ void split4(const float4& v, uint2& hi, uint2& lo) {
    uint32_t ux = __float_as_uint(v.x), uy = __float_as_uint(v.y);
    uint32_t uz = __float_as_uint(v.z), uw = __float_as_uint(v.w);
    hi.x = (ux >> 16) | (uy & 0xFFFF0000u);
    hi.y = (uz >> 16) | (uw & 0xFFFF0000u);
    float lx = v.x - __uint_as_float(ux & 0xFFFF0000u);
    float ly = v.y - __uint_as_float(uy & 0xFFFF0000u);
    float lz = v.z - __uint_as_float(uz & 0xFFFF0000u);
    float lw = v.w - __uint_as_float(uw & 0xFFFF0000u);
    __nv_bfloat162 l0 = __floats2bfloat162_rn(lx, ly);
    __nv_bfloat162 l1 = __floats2bfloat162_rn(lz, lw);
    lo.x = *reinterpret_cast<uint32_t*>(&l0);
    lo.y = *reinterpret_cast<uint32_t*>(&l1);
}

// ---------------------------------------------------------------------------
// bf16-split tensor-core GEMM, 2-stage smem pipeline, 1 sync/iter:
//   C[m,n] = scale * sum_k A[m,k]*B[n,k] (+ bias[n])
// A, B rows K-contiguous. Batched over z = bi*Hdim + hi.
// BM=128, BN in {128,64}, BK=32, 256 threads (8 warps).
// transV: store C transposed per-head ([B][H][DK][S]) for the V projection.
// ---------------------------------------------------------------------------
template <int BN>
__global__ __launch_bounds__(256) void gemm_mma(
    const float* __restrict__ A, const float* __restrict__ Bm,
    const float* __restrict__ bias, float* __restrict__ C,
    int K, int lda, int ldb, int ldc,
    long long sAb, long long sAh, long long sBb, long long sBh,
    long long sCb, long long sCh, int Hdim, float scale, int transV)
{
    constexpr int BM = 128, BK = 32;
    constexpr int SK = 40;                       // smem row stride in halves
    constexpr int NB4 = BN * BK / 4 / 256;       // B float4s per thread (4 or 2)
    constexpr int WGM = (BN == 128) ? 2 : 4;
    constexpr int WGN = (BN == 128) ? 4 : 2;
    constexpr int WM = BM / WGM, WN = BN / WGN;
    constexpr int MF = WM / 16, NF = WN / 8;
    constexpr uint32_t OFF_AL = BM * SK * 2;
    constexpr uint32_t OFF_BH = 2u * BM * SK * 2;
    constexpr uint32_t OFF_BL = OFF_BH + BN * SK * 2;
    constexpr uint32_t STAGE  = OFF_BL + BN * SK * 2;

    extern __shared__ char sm_raw[];
    const uint32_t sbase = smem_u32(sm_raw);

    const int bz = blockIdx.z;
    const int bi = bz / Hdim, hi2 = bz % Hdim;
    A  += (long long)bi * sAb + (long long)hi2 * sAh;
    Bm += (long long)bi * sBb + (long long)hi2 * sBh;
    C  += (long long)bi * sCb + (long long)hi2 * sCh;

    const int tid = threadIdx.x;
    const int wid = tid >> 5, lane = tid & 31;
    const int wm = (BN == 128) ? (wid >> 2) : (wid >> 1);
    const int wn = (BN == 128) ? (wid & 3) : (wid & 1);
    const int row0 = blockIdx.y * BM;
    const int col0 = blockIdx.x * BN;

    float acc[MF][NF][4];
#pragma unroll
    for (int i = 0; i < MF; i++)
#pragma unroll
        for (int j = 0; j < NF; j++)
#pragma unroll
            for (int c = 0; c < 4; c++) acc[i][j][c] = 0.0f;

    // ldmatrix per-thread row assignments
    const int a_row = wm * WM + (lane & 15);        // + mf*16
    const int a_kof = 8 * (lane >> 4);
    const int b_row = wn * WN + (lane & 7);         // + nf*8
    const int b_kof = 8 * ((lane >> 3) & 1);

    // per-thread smem store offsets (bytes): A float4 j -> row r, col c
    const int sa_r = tid >> 3, sa_c = (tid & 7) * 4;   // +j*32 rows
    // B: same pattern

    float4 a4[4], b4[NB4];

#define LOAD_A(KT)                                                              \
    _Pragma("unroll")                                                           \
    for (int j = 0; j < 4; j++) {                                               \
        a4[j] = *reinterpret_cast<const float4*>(                               \
            A + (long long)(row0 + sa_r + j * 32) * lda + (KT) + sa_c);         \
    }
#define LOAD_B(KT)                                                              \
    _Pragma("unroll")                                                           \
    for (int j = 0; j < NB4; j++) {                                             \
        b4[j] = *reinterpret_cast<const float4*>(                               \
            Bm + (long long)(col0 + sa_r + j * 32) * ldb + (KT) + sa_c);        \
    }
#define STORE_STAGE(S)                                                          \
    {                                                                           \
        const uint32_t sb = sbase + (uint32_t)(S) * STAGE;                      \
        _Pragma("unroll")                                                       \
        for (int j = 0; j < 4; j++) {                                           \
            uint2 h, l; split4(a4[j], h, l);                                    \
            uint32_t o = ((sa_r + j * 32) * SK + sa_c) * 2;                     \
            sts64(sb + o, h);                                                   \
            sts64(sb + OFF_AL + o, l);                                          \
        }                                                                       \
        _Pragma("unroll")                                                       \
        for (int j = 0; j < NB4; j++) {                                         \
            uint2 h, l; split4(b4[j], h, l);                                    \
            uint32_t o = ((sa_r + j * 32) * SK + sa_c) * 2;                     \
            sts64(sb + OFF_BH + o, h);                                          \
            sts64(sb + OFF_BL + o, l);                                          \
        }                                                                       \
    }

    const int nIter = K / BK;

    // Preamble: tile 0 -> stage 0; tile 1 -> regs
    LOAD_A(0); LOAD_B(0);
    STORE_STAGE(0);
    if (nIter > 1) { LOAD_A(BK); LOAD_B(BK); }
    __syncthreads();

    for (int i = 0; i < nIter; i++) {
        const int s = i & 1;
        if (i + 1 < nIter) STORE_STAGE(s ^ 1);           // STS drains during MMA
        if (i + 2 < nIter) { LOAD_A((i + 2) * BK); LOAD_B((i + 2) * BK); }

        const uint32_t sb = sbase + (uint32_t)s * STAGE;
#pragma unroll
        for (int ks = 0; ks < 2; ks++) {
            const int k16 = ks * 16;
            uint32_t bh[NF][2], bl[NF][2];
#pragma unroll
            for (int nf = 0; nf < NF; nf++) {
                uint32_t off = ((b_row + nf * 8) * SK + k16 + b_kof) * 2;
                ldmx2(bh[nf], sb + OFF_BH + off);
                ldmx2(bl[nf], sb + OFF_BL + off);
            }
#pragma unroll
            for (int mf = 0; mf < MF; mf++) {
                uint32_t ah[4], al[4];
                uint32_t off = ((a_row + mf * 16) * SK + k16 + a_kof) * 2;
                ldmx4(ah, sb + off);
                ldmx4(al, sb + OFF_AL + off);
#pragma unroll
                for (int nf = 0; nf < NF; nf++) {
                    mma16816(acc[mf][nf], ah, bh[nf]);   // hi*hi
                    mma16816(acc[mf][nf], ah, bl[nf]);   // hi*lo
                    mma16816(acc[mf][nf], al, bh[nf]);   // lo*hi
                }
            }
        }
        __syncthreads();
    }
#undef LOAD_A
#undef LOAD_B
#undef STORE_STAGE

    // Epilogue
#pragma unroll
    for (int mf = 0; mf < MF; mf++) {
#pragma unroll
        for (int nf = 0; nf < NF; nf++) {
            const int rg = row0 + wm * WM + mf * 16 + (lane >> 2);
            const int cg = col0 + wn * WN + nf * 8 + 2 * (lane & 3);
            if (!transV) {
                float2 v0, v1;
                v0.x = acc[mf][nf][0] * scale; v0.y = acc[mf][nf][1] * scale;
                v1.x = acc[mf][nf][2] * scale; v1.y = acc[mf][nf][3] * scale;
                if (bias) {
                    float bx = __ldg(bias + cg), by = __ldg(bias + cg + 1);
                    v0.x += bx; v0.y += by; v1.x += bx; v1.y += by;
                }
                *reinterpret_cast<float2*>(C + (long long)rg * ldc + cg) = v0;
                *reinterpret_cast<float2*>(C + (long long)(rg + 8) * ldc + cg) = v1;
            } else {
                // transposed per-head store: C[((b*H + h)*DK + d)*S + i]
#pragma unroll
                for (int e = 0; e < 4; e++) {
                    const int r = rg + (e >> 1) * 8;
                    const int n = cg + (e & 1);
                    float v = acc[mf][nf][e] * scale;
                    if (bias) v += __ldg(bias + n);
                    const int b = r >> 11, ii = r & 2047;
                    const long long idx =
                        (((long long)(b * H_ + (n >> 6)) * DK_ + (n & 63)) << 11) + ii;
                    C[idx] = v;
                }
            }
        }
    }
}

// ---------------------------------------------------------------------------
// Row softmax, row length 2048, register-resident.
// ---------------------------------------------------------------------------
__global__ __launch_bounds__(256) void softmax_rows2048(float* __restrict__ att)
{
    float4* p4 = reinterpret_cast<float4*>(att + (long long)blockIdx.x * 2048);
    const int tid = threadIdx.x;
    __shared__ float red[32];

    float4 v0 = p4[tid];
    float4 v1 = p4[tid + 256];

    float m = fmaxf(fmaxf(fmaxf(v0.x, v0.y), fmaxf(v0.z, v0.w)),
                    fmaxf(fmaxf(v1.x, v1.y), fmaxf(v1.z, v1.w)));
#pragma unroll
    for (int o = 16; o > 0; o >>= 1) m = fmaxf(m, __shfl_xor_sync(0xffffffffu, m, o));
    if ((tid & 31) == 0) red[tid >> 5] = m;
    __syncthreads();
    if (tid < 32) {
        float t = red[tid & 7];
#pragma unroll
        for (int o = 4; o > 0; o >>= 1) t = fmaxf(t, __shfl_xor_sync(0xffffffffu, t, o));
        red[tid & 7] = t;
    }
    __syncthreads();
    m = red[0];

    v0.x = __expf(v0.x - m); v0.y = __expf(v0.y - m);
    v0.z = __expf(v0.z - m); v0.w = __expf(v0.w - m);
    v1.x = __expf(v1.x - m); v1.y = __expf(v1.y - m);
    v1.z = __expf(v1.z - m); v1.w = __expf(v1.w - m);
    float s = v0.x + v0.y + v0.z + v0.w + v1.x + v1.y + v1.z + v1.w;
#pragma unroll
    for (int o = 16; o > 0; o >>= 1) s += __shfl_xor_sync(0xffffffffu, s, o);
    __syncthreads();
    if ((tid & 31) == 0) red[tid >> 5] = s;
    __syncthreads();
    if (tid < 32) {
        float t = red[tid & 7];
#pragma unroll
        for (int o = 4; o > 0; o >>= 1) t += __shfl_xor_sync(0xffffffffu, t, o);
        red[tid & 7] = t;
    }
    __syncthreads();
    const float inv = 1.0f / red[0];

    v0.x *= inv; v0.y *= inv; v0.z *= inv; v0.w *= inv;
    v1.x *= inv; v1.y *= inv; v1.z *= inv; v1.w *= inv;
    p4[tid] = v0;
    p4[tid + 256] = v1;
}

extern "C" void kernel_launch(void* const* d_in, const int* in_sizes, int n_in,
                              void* d_out, int out_size)
{
    const float* q  = (const float*)d_in[0];
    const float* k  = (const float*)d_in[1];
    const float* v  = (const float*)d_in[2];
    const float* Wq = (const float*)d_in[3];
    const float* bq = (const float*)d_in[4];
    const float* Wk = (const float*)d_in[5];
    const float* bk = (const float*)d_in[6];
    const float* Wv = (const float*)d_in[7];
    const float* bv = (const float*)d_in[8];
    const float* Wo = (const float*)d_in[9];
    const float* bo = (const float*)d_in[10];
    float* out = (float*)d_out;

    float *qp, *kp, *vt, *attn;
    cudaGetSymbolAddress((void**)&qp, g_q);
    cudaGetSymbolAddress((void**)&kp, g_k);
    cudaGetSymbolAddress((void**)&vt, g_v);
    if ((long long)out_size >= BSD_LL + ATTN_LL) {
        attn = out + BSD_LL;                 // tuple output: (out, attn)
    } else {
        cudaGetSymbolAddress((void**)&attn, g_attn_fallback);
    }
    float* ctx = qp;  // reuse g_q after logits are done

    // dynamic smem: 2 stages * (A hi/lo + B hi/lo)
    const int SM128 = 2 * (2 * 128 * 40 * 2 + 2 * 128 * 40 * 2);  // 81920
    const int SM64  = 2 * (2 * 128 * 40 * 2 + 2 * 64  * 40 * 2);  // 61440
    cudaFuncSetAttribute(gemm_mma<128>, cudaFuncAttributeMaxDynamicSharedMemorySize, SM128);
    cudaFuncSetAttribute(gemm_mma<64>,  cudaFuncAttributeMaxDynamicSharedMemorySize, SM64);

    const float inv_sqrt_dk = 0.125f; // 1/sqrt(64)

    // 1) Projections: [8192,1024] = X @ W^T + b
    {
        dim3 grid(D_ / 128, (int)(BS_LL / 128), 1);
        gemm_mma<128><<<grid, 256, SM128>>>(
            q, Wq, bq, qp, D_, D_, D_, D_, 0,0,0,0,0,0, 1, 1.0f, 0);
        gemm_mma<128><<<grid, 256, SM128>>>(
            k, Wk, bk, kp, D_, D_, D_, D_, 0,0,0,0,0,0, 1, 1.0f, 0);
        gemm_mma<128><<<grid, 256, SM128>>>(
            v, Wv, bv, vt, D_, D_, D_, D_, 0,0,0,0,0,0, 1, 1.0f, 1);  // transposed store
    }

    // 2) Logits: attn[b,h,i,j] = scale * dot(Qp[b,i,h*64:], Kp[b,j,h*64:])
    {
        dim3 grid(S_ / 128, S_ / 128, B_ * H_);
        gemm_mma<128><<<grid, 256, SM128>>>(
            qp, kp, nullptr, attn, DK_, D_, D_, S_,
            (long long)S_ * D_, DK_,
            (long long)S_ * D_, DK_,
            (long long)H_ * S_ * S_, (long long)S_ * S_,
            H_, inv_sqrt_dk, 0);
    }

    // 3) Softmax over last dim, in place
    softmax_rows2048<<<(unsigned)(B_ * H_ * S_), 256>>>(attn);

    // 4) Ctx: ctx[b,i,h*64+d] = sum_j attn[b,h,i,j] * Vt[b,h,d,j]
    {
        dim3 grid(1, S_ / 128, B_ * H_);
        gemm_mma<64><<<grid, 256, SM64>>>(
            attn, vt, nullptr, ctx, S_, S_, S_, D_,
            (long long)H_ * S_ * S_, (long long)S_ * S_,
            (long long)S_ * D_, (long long)DK_ * S_,
            (long long)S_ * D_, (long long)DK_,
            H_, 1.0f, 0);
    }

    // 5) Output projection: out = ctx @ Wo^T + bo
    {
        dim3 grid(D_ / 128, (int)(BS_LL / 128), 1);
        gemm_mma<128><<<grid, 256, SM128>>>(
            ctx, Wo, bo, out, D_, D_, D_, D_, 0,0,0,0,0,0, 1, 1.0f, 0);
    }
}